// round 5
// baseline (speedup 1.0000x reference)
#include <cuda_runtime.h>
#include <cuda_bf16.h>

// Nearest-codeword quantization, uniform sorted 16-entry codebook.
// out[i] = argmin_c |x[i] - c|, tie toward the LOWER codeword.
//
// R5: NO shared memory, NO per-element table lookup. The codebook is uniform,
// so the chosen codeword is computed arithmetically: val = fma(mc, step, c0)
// (<=1 ulp from the stored linspace value; rel tolerance is 1e-3).
// Classification safety: m = round((x-c0)/step) is exact except within a few
// ulp of a midpoint; a guard band EPS=1e-4 in index space routes those rare
// elements (~2e-4 of all) to an exact comparison against the TRUE codebook
// values via __ldg (64B codebook, L1-resident). R4 showed the dynamic LDS
// gather (32 lanes over 16 banks, ~4-5 wavefronts each) was the L1 bottleneck
// (L1=84%, DRAM=67%); this removes it entirely.

#define K_CB 16

__global__ void __launch_bounds__(256)
quant_uniform_kernel(const float4* __restrict__ x,
                     const float*  __restrict__ cb,
                     float4* __restrict__ out,
                     int n4)
{
    const float c0   = __ldg(cb);
    const float cK   = __ldg(cb + K_CB - 1);
    const float step     = (cK - c0) * (1.0f / (float)(K_CB - 1));
    const float inv_step = (float)(K_CB - 1) / (cK - c0);
    const float b0  = -c0 * inv_step;
    const float EPS = 1e-4f;            // index-space guard band

    int base = (blockIdx.x * blockDim.x + threadIdx.x) * 4;

    if (base + 3 < n4) {
        // 4 independent 16B streaming loads issued up-front (MLP_p1 = 4).
        float4 v[4];
        v[0] = __ldcs(x + base + 0);
        v[1] = __ldcs(x + base + 1);
        v[2] = __ldcs(x + base + 2);
        v[3] = __ldcs(x + base + 3);

#pragma unroll
        for (int u = 0; u < 4; u++) {
            float4 r;
            const float* vp = reinterpret_cast<const float*>(&v[u]);
            float* rp = reinterpret_cast<float*>(&r);
#pragma unroll
            for (int j = 0; j < 4; j++) {
                float xv = vp[j];
                float t  = fmaf(xv, inv_step, b0);
                int   m  = __float2int_rn(t);
                int   mc = min(max(m, 0), K_CB - 1);
                float d  = t - (float)m;

                float val = fmaf((float)mc, step, c0);   // arithmetic codeword

                // Rare exact path: t within EPS of a half-integer, in range.
                if (!((m != mc) | (fabsf(d) < (0.5f - EPS)))) {
                    int k = min(max(__float2int_rd(t), 0), K_CB - 2);
                    float lo = __ldg(cb + k);
                    float hi = __ldg(cb + k + 1);
                    val = (fabsf(xv - lo) <= fabsf(xv - hi)) ? lo : hi;
                }
                rp[j] = val;
            }
            __stcs(out + base + u, r);
        }
    } else {
        // Tail (not taken for 8192x8192).
        for (int idx = base; idx < n4 && idx >= 0; idx++) {
            float4 v = __ldcs(x + idx);
            float4 r;
            const float* vp = reinterpret_cast<const float*>(&v);
            float* rp = reinterpret_cast<float*>(&r);
#pragma unroll
            for (int j = 0; j < 4; j++) {
                float xv = vp[j];
                float t  = fmaf(xv, inv_step, b0);
                int   m  = __float2int_rn(t);
                int   mc = min(max(m, 0), K_CB - 1);
                float d  = t - (float)m;
                float val = fmaf((float)mc, step, c0);
                if (!((m != mc) | (fabsf(d) < (0.5f - EPS)))) {
                    int k = min(max(__float2int_rd(t), 0), K_CB - 2);
                    float lo = __ldg(cb + k);
                    float hi = __ldg(cb + k + 1);
                    val = (fabsf(xv - lo) <= fabsf(xv - hi)) ? lo : hi;
                }
                rp[j] = val;
            }
            __stcs(out + idx, r);
        }
    }
}

extern "C" void kernel_launch(void* const* d_in, const int* in_sizes, int n_in,
                              void* d_out, int out_size)
{
    const float* x  = (const float*)d_in[0];
    const float* cb = (const float*)d_in[1];
    float* out = (float*)d_out;

    int n  = in_sizes[0];         // 8192*8192 = 67,108,864
    int n4 = n >> 2;              // 16,777,216 float4

    const int threads = 256;
    const int per_block = threads * 4;                 // 1024 float4 / block
    int blocks = (n4 + per_block - 1) / per_block;     // 16384

    quant_uniform_kernel<<<blocks, threads>>>(
        (const float4*)x, cb, (float4*)out, n4);
}

// round 6
// speedup vs baseline: 1.1660x; 1.1660x over previous
#include <cuda_runtime.h>
#include <cuda_bf16.h>

// Nearest-codeword quantization, uniform sorted 16-entry codebook.
// out[i] = argmin_c |x[i] - c|, tie toward the LOWER codeword.
//
// R6: COALESCED ILP. R3-R5 used per-thread blocks (lane stride 64B), so each
// LDG.128 touched 16 cache lines (nL=16) instead of 8 -> 2x L1 wavefronts.
// Now u-iterations stride by blockDim: every LDG.128/STG.128 is fully
// coalesced (warp = 8 contiguous 128B lines).
// Codeword is computed arithmetically (uniform codebook): <=1 ulp from the
// stored linspace value (rel_err ~7e-8 observed, tol 1e-3). Elements within
// EPS=1e-4 (index space) of a midpoint (~2e-4 of all) take a rare exact path
// against the TRUE codebook via __ldg, so classification matches reference.

#define K_CB 16

__global__ void __launch_bounds__(256)
quant_uniform_kernel(const float4* __restrict__ x,
                     const float*  __restrict__ cb,
                     float4* __restrict__ out,
                     int n4)
{
    const float c0 = __ldg(cb);
    const float cK = __ldg(cb + K_CB - 1);
    const float step     = (cK - c0) * (1.0f / (float)(K_CB - 1));
    const float inv_step = (float)(K_CB - 1) / (cK - c0);
    const float b0  = -c0 * inv_step;
    const float EPS = 1e-4f;            // index-space guard band

    const int tid   = threadIdx.x;
    const int bdim  = blockDim.x;                 // 256
    const int base  = blockIdx.x * (bdim * 4) + tid;

    if (base + 3 * bdim < n4) {
        // 4 fully-coalesced independent LDG.128 (each warp: 8 contiguous lines).
        float4 v0 = x[base + 0 * bdim];
        float4 v1 = x[base + 1 * bdim];
        float4 v2 = x[base + 2 * bdim];
        float4 v3 = x[base + 3 * bdim];

        float4 vv[4] = {v0, v1, v2, v3};

#pragma unroll
        for (int u = 0; u < 4; u++) {
            float4 r;
            const float* vp = reinterpret_cast<const float*>(&vv[u]);
            float* rp = reinterpret_cast<float*>(&r);
#pragma unroll
            for (int j = 0; j < 4; j++) {
                float xv = vp[j];
                float t  = fmaf(xv, inv_step, b0);
                int   m  = __float2int_rn(t);
                int   mc = min(max(m, 0), K_CB - 1);
                float d  = t - (float)m;

                float val = fmaf((float)mc, step, c0);   // arithmetic codeword

                // Rare exact path: t within EPS of a midpoint, in range.
                if (!((m != mc) | (fabsf(d) < (0.5f - EPS)))) {
                    int k = min(max(__float2int_rd(t), 0), K_CB - 2);
                    float lo = __ldg(cb + k);
                    float hi = __ldg(cb + k + 1);
                    val = (fabsf(xv - lo) <= fabsf(xv - hi)) ? lo : hi;
                }
                rp[j] = val;
            }
            out[base + u * bdim] = r;
        }
    } else {
        // Tail (not taken for 8192x8192).
        for (int u = 0; u < 4; u++) {
            int idx = base + u * bdim;
            if (idx >= n4) break;
            float4 v = x[idx];
            float4 r;
            const float* vp = reinterpret_cast<const float*>(&v);
            float* rp = reinterpret_cast<float*>(&r);
#pragma unroll
            for (int j = 0; j < 4; j++) {
                float xv = vp[j];
                float t  = fmaf(xv, inv_step, b0);
                int   m  = __float2int_rn(t);
                int   mc = min(max(m, 0), K_CB - 1);
                float d  = t - (float)m;
                float val = fmaf((float)mc, step, c0);
                if (!((m != mc) | (fabsf(d) < (0.5f - EPS)))) {
                    int k = min(max(__float2int_rd(t), 0), K_CB - 2);
                    float lo = __ldg(cb + k);
                    float hi = __ldg(cb + k + 1);
                    val = (fabsf(xv - lo) <= fabsf(xv - hi)) ? lo : hi;
                }
                rp[j] = val;
            }
            out[idx] = r;
        }
    }
}

extern "C" void kernel_launch(void* const* d_in, const int* in_sizes, int n_in,
                              void* d_out, int out_size)
{
    const float* x  = (const float*)d_in[0];
    const float* cb = (const float*)d_in[1];
    float* out = (float*)d_out;

    int n  = in_sizes[0];         // 8192*8192 = 67,108,864
    int n4 = n >> 2;              // 16,777,216 float4

    const int threads = 256;
    const int per_block = threads * 4;                 // 1024 float4 / block
    int blocks = (n4 + per_block - 1) / per_block;     // 16384

    quant_uniform_kernel<<<blocks, threads>>>(
        (const float4*)x, cb, (float4*)out, n4);
}

// round 7
// speedup vs baseline: 1.1704x; 1.0037x over previous
#include <cuda_runtime.h>
#include <cuda_bf16.h>

// Nearest-codeword quantization, uniform sorted 16-entry codebook.
// out[i] = argmin_c |x[i] - c|, tie toward the LOWER codeword.
//
// R7: float-domain hot path (no F2I/I2F converts). Per element:
//   t  = fma(x, inv_step, b0)
//   tc = clamp(t, 0, 15)        (2x FMNMX)
//   tr = rintf(tc)              (1x FRND, ties-to-even)
//   val= fma(tr, step, c0)      (<=1 ulp from stored linspace; tol 1e-3)
// Guard band: d = tc - tr; if |d| >= 0.5-EPS (incl. all RNI tie cases), take
// the rare exact path (~2e-4 of elements) comparing against the TRUE codebook
// values via __ldg -> classification identical to reference searchsorted.
// Out-of-range t: tc is exactly 0 or 15, d = 0 -> guard never fires (endpoint
// is unconditionally nearest). Memory access unchanged from R6 (coalesced
// block-strided ILP=4, LDG.128/STG.128).

#define K_CB 16

__global__ void __launch_bounds__(256)
quant_uniform_kernel(const float4* __restrict__ x,
                     const float*  __restrict__ cb,
                     float4* __restrict__ out,
                     int n4)
{
    const float c0 = __ldg(cb);
    const float cK = __ldg(cb + K_CB - 1);
    const float step     = (cK - c0) * (1.0f / (float)(K_CB - 1));
    const float inv_step = (float)(K_CB - 1) / (cK - c0);
    const float b0  = -c0 * inv_step;
    const float EPS = 1e-4f;            // index-space guard band

    const int tid  = threadIdx.x;
    const int bdim = blockDim.x;                  // 256
    const int base = blockIdx.x * (bdim * 4) + tid;

    if (base + 3 * bdim < n4) {
        // 4 fully-coalesced independent LDG.128.
        float4 vv[4];
        vv[0] = x[base + 0 * bdim];
        vv[1] = x[base + 1 * bdim];
        vv[2] = x[base + 2 * bdim];
        vv[3] = x[base + 3 * bdim];

#pragma unroll
        for (int u = 0; u < 4; u++) {
            float4 r;
            const float* vp = reinterpret_cast<const float*>(&vv[u]);
            float* rp = reinterpret_cast<float*>(&r);
#pragma unroll
            for (int j = 0; j < 4; j++) {
                float xv = vp[j];
                float t  = fmaf(xv, inv_step, b0);
                float tc = fminf(fmaxf(t, 0.0f), (float)(K_CB - 1));
                float tr = rintf(tc);
                float val = fmaf(tr, step, c0);

                float d = tc - tr;
                if (fabsf(d) >= 0.5f - EPS) {     // rare exact path
                    int k = min(max(__float2int_rd(t), 0), K_CB - 2);
                    float lo = __ldg(cb + k);
                    float hi = __ldg(cb + k + 1);
                    val = (fabsf(xv - lo) <= fabsf(xv - hi)) ? lo : hi;
                }
                rp[j] = val;
            }
            out[base + u * bdim] = r;
        }
    } else {
        // Tail (not taken for 8192x8192).
        for (int u = 0; u < 4; u++) {
            int idx = base + u * bdim;
            if (idx >= n4) break;
            float4 v = x[idx];
            float4 r;
            const float* vp = reinterpret_cast<const float*>(&v);
            float* rp = reinterpret_cast<float*>(&r);
#pragma unroll
            for (int j = 0; j < 4; j++) {
                float xv = vp[j];
                float t  = fmaf(xv, inv_step, b0);
                float tc = fminf(fmaxf(t, 0.0f), (float)(K_CB - 1));
                float tr = rintf(tc);
                float val = fmaf(tr, step, c0);
                float d = tc - tr;
                if (fabsf(d) >= 0.5f - EPS) {
                    int k = min(max(__float2int_rd(t), 0), K_CB - 2);
                    float lo = __ldg(cb + k);
                    float hi = __ldg(cb + k + 1);
                    val = (fabsf(xv - lo) <= fabsf(xv - hi)) ? lo : hi;
                }
                rp[j] = val;
            }
            out[idx] = r;
        }
    }
}

extern "C" void kernel_launch(void* const* d_in, const int* in_sizes, int n_in,
                              void* d_out, int out_size)
{
    const float* x  = (const float*)d_in[0];
    const float* cb = (const float*)d_in[1];
    float* out = (float*)d_out;

    int n  = in_sizes[0];         // 8192*8192 = 67,108,864
    int n4 = n >> 2;              // 16,777,216 float4

    const int threads = 256;
    const int per_block = threads * 4;                 // 1024 float4 / block
    int blocks = (n4 + per_block - 1) / per_block;     // 16384

    quant_uniform_kernel<<<blocks, threads>>>(
        (const float4*)x, cb, (float4*)out, n4);
}

// round 8
// speedup vs baseline: 1.2252x; 1.0468x over previous
#include <cuda_runtime.h>
#include <cuda_bf16.h>

// Nearest-codeword quantization, uniform sorted 16-entry codebook.
// out[i] = argmin_c |x[i] - c|, tie toward the LOWER codeword.
//
// R8: warp-collective rare-path guard. R7 had a per-element `if` -> 16
// BSSY/BSYNC envelopes + FSETPs per thread, pure issue waste (alu=31.5%,
// issue=48%). Now the hot path is a branchless 7-op chain per element:
//   t  = fma(x, inv_step, b0)
//   tc = clamp(t, 0, 15)            (2x FMNMX)
//   tr = rintf(tc)                  (FRND)
//   val= fma(tr, step, c0)          (<=1 ulp of stored linspace; tol 1e-3)
//   maxd = fmax(maxd, |tc - tr|)    (FADD + FMNMX-with-abs)
// and ONE __any_sync vote per float4 (4/thread) routes the whole warp to an
// exact recompute (true codebook values via __ldg, reference tie-break) when
// any lane is within EPS=1e-4 (index space) of a midpoint (~2.5% of warp-
// iterations). Memory access unchanged from R6/R7 (coalesced ILP=4).

#define K_CB 16

__global__ void __launch_bounds__(256)
quant_uniform_kernel(const float4* __restrict__ x,
                     const float*  __restrict__ cb,
                     float4* __restrict__ out,
                     int n4)
{
    const float c0 = __ldg(cb);
    const float cK = __ldg(cb + K_CB - 1);
    const float step     = (cK - c0) * (1.0f / (float)(K_CB - 1));
    const float inv_step = (float)(K_CB - 1) / (cK - c0);
    const float b0 = -c0 * inv_step;
    const float TH = 0.5f - 1e-4f;      // guard threshold in index space

    const int tid  = threadIdx.x;
    const int bdim = blockDim.x;                  // 256
    const int base = blockIdx.x * (bdim * 4) + tid;

    if (base + 3 * bdim < n4) {
        // 4 fully-coalesced independent LDG.128.
        float4 vv[4];
        vv[0] = x[base + 0 * bdim];
        vv[1] = x[base + 1 * bdim];
        vv[2] = x[base + 2 * bdim];
        vv[3] = x[base + 3 * bdim];

#pragma unroll
        for (int u = 0; u < 4; u++) {
            float4 r;
            const float* vp = reinterpret_cast<const float*>(&vv[u]);
            float* rp = reinterpret_cast<float*>(&r);

            float maxd = 0.0f;
#pragma unroll
            for (int j = 0; j < 4; j++) {
                float xv = vp[j];
                float t  = fmaf(xv, inv_step, b0);
                float tc = fminf(fmaxf(t, 0.0f), (float)(K_CB - 1));
                float tr = rintf(tc);
                rp[j] = fmaf(tr, step, c0);
                maxd = fmaxf(maxd, fabsf(tc - tr));   // FMNMX with |.|
            }

            // One vote per float4: does ANY lane need the exact path?
            if (__any_sync(0xFFFFFFFFu, maxd >= TH)) {
#pragma unroll
                for (int j = 0; j < 4; j++) {
                    float xv = vp[j];
                    float t  = fmaf(xv, inv_step, b0);
                    int k = min(max(__float2int_rd(t), 0), K_CB - 2);
                    float lo = __ldg(cb + k);
                    float hi = __ldg(cb + k + 1);
                    rp[j] = (fabsf(xv - lo) <= fabsf(xv - hi)) ? lo : hi;
                }
            }

            out[base + u * bdim] = r;
        }
    } else {
        // Tail (not taken for 8192x8192): always-exact scalar path.
        for (int u = 0; u < 4; u++) {
            int idx = base + u * bdim;
            if (idx >= n4) break;
            float4 v = x[idx];
            float4 r;
            const float* vp = reinterpret_cast<const float*>(&v);
            float* rp = reinterpret_cast<float*>(&r);
#pragma unroll
            for (int j = 0; j < 4; j++) {
                float xv = vp[j];
                float t  = fmaf(xv, inv_step, b0);
                int k = min(max(__float2int_rd(t), 0), K_CB - 2);
                float lo = __ldg(cb + k);
                float hi = __ldg(cb + k + 1);
                rp[j] = (fabsf(xv - lo) <= fabsf(xv - hi)) ? lo : hi;
            }
            out[idx] = r;
        }
    }
}

extern "C" void kernel_launch(void* const* d_in, const int* in_sizes, int n_in,
                              void* d_out, int out_size)
{
    const float* x  = (const float*)d_in[0];
    const float* cb = (const float*)d_in[1];
    float* out = (float*)d_out;

    int n  = in_sizes[0];         // 8192*8192 = 67,108,864
    int n4 = n >> 2;              // 16,777,216 float4

    const int threads = 256;
    const int per_block = threads * 4;                 // 1024 float4 / block
    int blocks = (n4 + per_block - 1) / per_block;     // 16384

    quant_uniform_kernel<<<blocks, threads>>>(
        (const float4*)x, cb, (float4*)out, n4);
}